// round 4
// baseline (speedup 1.0000x reference)
#include <cuda_runtime.h>
#include <math.h>

#define BB 64
#define SS 2048
#define HH 128
#define MM (BB*SS)   // 131072

// Scratch (no cudaMalloc allowed): xi = x@Wi + b, and h history.
__device__ float g_xi[BB * SS * HH];
__device__ float g_h [BB * SS * HH];

// ---------------------------------------------------------------------------
// Packed f32x2 helpers (FFMA2 is only reachable from PTX fma.rn.f32x2).
// ---------------------------------------------------------------------------
__device__ __forceinline__ unsigned long long pack2(float lo, float hi) {
    unsigned long long r;
    asm("mov.b64 %0, {%1, %2};" : "=l"(r) : "f"(lo), "f"(hi));
    return r;
}
__device__ __forceinline__ void fma2(unsigned long long& a,
                                     unsigned long long b,
                                     unsigned long long c) {
    asm("fma.rn.f32x2 %0, %1, %2, %0;" : "+l"(a) : "l"(b), "l"(c));
}
__device__ __forceinline__ float2 unpack2(unsigned long long a) {
    float2 f;
    asm("mov.b64 {%0, %1}, %2;" : "=f"(f.x), "=f"(f.y) : "l"(a));
    return f;
}

// ---------------------------------------------------------------------------
// Generic GEMM for K=128, N=128:  C[M,128] = A[M,128] @ W[128,128] + bias[128]
// Tile: 64 rows x 128 cols per CTA, 256 threads, full K resident in shared.
// ---------------------------------------------------------------------------
__global__ __launch_bounds__(256) void gemm_k128(const float* __restrict__ A,
                                                 const float* __restrict__ W,
                                                 const float* __restrict__ bias,
                                                 float* __restrict__ C) {
    extern __shared__ float smem[];
    float* sW = smem;              // 128*128 floats, no pad
    float* sA = smem + 128 * 128;  // 64 rows, pitch 132 (pad kills bank conflicts)

    const int tid  = threadIdx.x;
    const int row0 = blockIdx.x * 64;

    // Load W (128x128) into shared, vectorized.
    {
        const float4* Wg  = (const float4*)W;
        float4*       sW4 = (float4*)sW;
#pragma unroll
        for (int i = 0; i < 16; i++)
            sW4[tid + i * 256] = Wg[tid + i * 256];
    }
    // Load A tile (64x128) into shared with pitch 132.
    {
        const float4* Ag = (const float4*)(A + (size_t)row0 * 128);
#pragma unroll
        for (int i = 0; i < 8; i++) {
            int f4 = tid + i * 256;      // 0..2047
            int r  = f4 >> 5;            // row 0..63
            int c4 = f4 & 31;            // float4 col 0..31
            float4 v = Ag[f4];
            *(float4*)(sA + r * 132 + c4 * 4) = v;
        }
    }
    __syncthreads();

    const int tx = tid & 15;   // 16 column groups
    const int ty = tid >> 4;   // 16 row groups (4 rows each)

    float acc[4][8];
#pragma unroll
    for (int r = 0; r < 4; r++)
#pragma unroll
        for (int c = 0; c < 8; c++) acc[r][c] = 0.f;

#pragma unroll 4
    for (int k = 0; k < 128; k++) {
        float a0 = sA[(ty * 4 + 0) * 132 + k];
        float a1 = sA[(ty * 4 + 1) * 132 + k];
        float a2 = sA[(ty * 4 + 2) * 132 + k];
        float a3 = sA[(ty * 4 + 3) * 132 + k];
        float bv[8];
#pragma unroll
        for (int c = 0; c < 8; c++) bv[c] = sW[k * 128 + tx + 16 * c];
#pragma unroll
        for (int c = 0; c < 8; c++) {
            acc[0][c] = fmaf(a0, bv[c], acc[0][c]);
            acc[1][c] = fmaf(a1, bv[c], acc[1][c]);
            acc[2][c] = fmaf(a2, bv[c], acc[2][c]);
            acc[3][c] = fmaf(a3, bv[c], acc[3][c]);
        }
    }

#pragma unroll
    for (int c = 0; c < 8; c++) {
        float bv = bias[tx + 16 * c];
#pragma unroll
        for (int r = 0; r < 4; r++) {
            C[(size_t)(row0 + ty * 4 + r) * 128 + tx + 16 * c] = acc[r][c] + bv;
        }
    }
}

// ---------------------------------------------------------------------------
// Recurrence: one CTA per batch sequence. Thread j owns output column j and
// keeps Wh[:,j] packed f32x2 in registers. h double-buffered in shared:
// read buf cur, write buf cur^1, ONE barrier per step.
// h_t = relu(tanh(xi_t + h_{t-1} @ Wh)); history written to g_h.
// ---------------------------------------------------------------------------
__global__ __launch_bounds__(128) void rnn_kernel(const float* __restrict__ Wh) {
    __shared__ __align__(16) float sh[2][HH];
    const int b = blockIdx.x;
    const int j = threadIdx.x;

    // Wh column j, packed as 64 f32x2 registers (coalesced global loads).
    unsigned long long w2[HH / 2];
#pragma unroll
    for (int k2 = 0; k2 < HH / 2; k2++)
        w2[k2] = pack2(Wh[(2 * k2) * HH + j], Wh[(2 * k2 + 1) * HH + j]);

    sh[0][j] = 0.f;
    const float* xip = g_xi + (size_t)b * SS * HH + j;
    float*       hp  = g_h  + (size_t)b * SS * HH + j;
    __syncthreads();

    float xi_cur = xip[0];
    int cur = 0;
    for (int s = 0; s < SS; s++) {
        // Prefetch next step's xi (hides L2/DRAM latency behind the matvec).
        float xi_next = (s + 1 < SS) ? xip[(size_t)(s + 1) * HH] : 0.f;

        // 8 scalar chains as 4 packed accumulators; 64 FFMA2 total.
        unsigned long long acc0 = 0ull, acc1 = 0ull, acc2 = 0ull, acc3 = 0ull;
        const ulonglong2* sh2 = (const ulonglong2*)sh[cur];
#pragma unroll
        for (int k4 = 0; k4 < HH / 4; k4++) {
            ulonglong2 hv = sh2[k4];           // LDS.128 -> two packed f32x2
            if (k4 & 1) {
                fma2(acc2, hv.x, w2[2 * k4]);
                fma2(acc3, hv.y, w2[2 * k4 + 1]);
            } else {
                fma2(acc0, hv.x, w2[2 * k4]);
                fma2(acc1, hv.y, w2[2 * k4 + 1]);
            }
        }
        float2 f0 = unpack2(acc0), f1 = unpack2(acc1);
        float2 f2 = unpack2(acc2), f3 = unpack2(acc3);
        float v = xi_cur + (((f0.x + f0.y) + (f1.x + f1.y)) +
                            ((f2.x + f2.y) + (f3.x + f3.y)));

        // tanh(v) = 1 - 2/(exp(2v)+1) via MUFU.EX2 + MUFU.RCP (~1e-6 rel err).
        float vc = fminf(fmaxf(v, -15.f), 15.f);
        float e;
        asm("ex2.approx.f32 %0, %1;" : "=f"(e) : "f"(vc * 2.885390082f));
        float r;
        asm("rcp.approx.f32 %0, %1;" : "=f"(r) : "f"(e + 1.f));
        float t  = fmaf(-2.f, r, 1.f);
        float hn = fmaxf(t, 0.f);

        sh[cur ^ 1][j] = hn;          // write the OTHER buffer
        hp[(size_t)s * HH] = hn;      // history for the output GEMM
        xi_cur = xi_next;
        __syncthreads();              // single barrier: write -> next read
        cur ^= 1;
    }
}

extern "C" void kernel_launch(void* const* d_in, const int* in_sizes, int n_in,
                              void* d_out, int out_size) {
    const float* x  = (const float*)d_in[0];
    const float* Wi = (const float*)d_in[1];
    const float* Wh = (const float*)d_in[2];
    const float* b  = (const float*)d_in[3];
    const float* Wo = (const float*)d_in[4];
    const float* bo = (const float*)d_in[5];
    float* y = (float*)d_out;

    float* xi_ptr = nullptr;
    float* h_ptr  = nullptr;
    cudaGetSymbolAddress((void**)&xi_ptr, g_xi);
    cudaGetSymbolAddress((void**)&h_ptr,  g_h);

    const size_t smem = (128 * 128 + 64 * 132) * sizeof(float);  // ~97 KB
    cudaFuncSetAttribute(gemm_k128, cudaFuncAttributeMaxDynamicSharedMemorySize,
                         (int)smem);

    // 1) xi = x @ Wi + b
    gemm_k128<<<MM / 64, 256, smem>>>(x, Wi, b, xi_ptr);
    // 2) sequential recurrence (parallel over batch)
    rnn_kernel<<<BB, 128>>>(Wh);
    // 3) y = h @ Wo + bo
    gemm_k128<<<MM / 64, 256, smem>>>(h_ptr, Wo, bo, y);
}

// round 5
// speedup vs baseline: 1.2720x; 1.2720x over previous
#include <cuda_runtime.h>
#include <math.h>

#define BB 64
#define SS 2048
#define HH 128
#define MM (BB*SS)   // 131072

// Scratch (no cudaMalloc allowed): xi = x@Wi + b, and h history.
__device__ float g_xi[BB * SS * HH];
__device__ float g_h [BB * SS * HH];

// ---------------------------------------------------------------------------
// Generic GEMM for K=128, N=128:  C[M,128] = A[M,128] @ W[128,128] + bias[128]
// Tile: 64 rows x 128 cols per CTA, 256 threads, full K resident in shared.
// ---------------------------------------------------------------------------
__global__ __launch_bounds__(256) void gemm_k128(const float* __restrict__ A,
                                                 const float* __restrict__ W,
                                                 const float* __restrict__ bias,
                                                 float* __restrict__ C) {
    extern __shared__ float smem[];
    float* sW = smem;              // 128*128 floats, no pad
    float* sA = smem + 128 * 128;  // 64 rows, pitch 132 (pad kills bank conflicts)

    const int tid  = threadIdx.x;
    const int row0 = blockIdx.x * 64;

    // Load W (128x128) into shared, vectorized.
    {
        const float4* Wg  = (const float4*)W;
        float4*       sW4 = (float4*)sW;
#pragma unroll
        for (int i = 0; i < 16; i++)
            sW4[tid + i * 256] = Wg[tid + i * 256];
    }
    // Load A tile (64x128) into shared with pitch 132.
    {
        const float4* Ag = (const float4*)(A + (size_t)row0 * 128);
#pragma unroll
        for (int i = 0; i < 8; i++) {
            int f4 = tid + i * 256;      // 0..2047
            int r  = f4 >> 5;            // row 0..63
            int c4 = f4 & 31;            // float4 col 0..31
            float4 v = Ag[f4];
            *(float4*)(sA + r * 132 + c4 * 4) = v;
        }
    }
    __syncthreads();

    const int tx = tid & 15;   // 16 column groups
    const int ty = tid >> 4;   // 16 row groups (4 rows each)

    float acc[4][8];
#pragma unroll
    for (int r = 0; r < 4; r++)
#pragma unroll
        for (int c = 0; c < 8; c++) acc[r][c] = 0.f;

#pragma unroll 4
    for (int k = 0; k < 128; k++) {
        float a0 = sA[(ty * 4 + 0) * 132 + k];
        float a1 = sA[(ty * 4 + 1) * 132 + k];
        float a2 = sA[(ty * 4 + 2) * 132 + k];
        float a3 = sA[(ty * 4 + 3) * 132 + k];
        float bv[8];
#pragma unroll
        for (int c = 0; c < 8; c++) bv[c] = sW[k * 128 + tx + 16 * c];
#pragma unroll
        for (int c = 0; c < 8; c++) {
            acc[0][c] = fmaf(a0, bv[c], acc[0][c]);
            acc[1][c] = fmaf(a1, bv[c], acc[1][c]);
            acc[2][c] = fmaf(a2, bv[c], acc[2][c]);
            acc[3][c] = fmaf(a3, bv[c], acc[3][c]);
        }
    }

#pragma unroll
    for (int c = 0; c < 8; c++) {
        float bv = bias[tx + 16 * c];
#pragma unroll
        for (int r = 0; r < 4; r++) {
            C[(size_t)(row0 + ty * 4 + r) * 128 + tx + 16 * c] = acc[r][c] + bv;
        }
    }
}

// ---------------------------------------------------------------------------
// Recurrence: one CTA per batch sequence, 256 threads.
// Thread t -> column j = t>>1, K-half = t&1. Each thread: 64 scalar FFMAs with
// its half of Wh[:,j] in registers; halves combined with shfl.bfly(1) (the two
// halves of a column sit in adjacent lanes of the same warp -> no barrier).
// h double-buffered in shared: ONE __syncthreads per step.
// h_t = relu(tanh(xi_t + h_{t-1} @ Wh)); history written to g_h.
// ---------------------------------------------------------------------------
__global__ __launch_bounds__(256) void rnn_kernel(const float* __restrict__ Wh) {
    __shared__ __align__(16) float sh[2][HH];
    const int b    = blockIdx.x;
    const int t    = threadIdx.x;
    const int j    = t >> 1;    // output column 0..127
    const int half = t & 1;     // K-half 0..1

    // This thread's 64 weights: Wh[k*128 + j], k in [64*half, 64*half+64).
    float w[64];
#pragma unroll
    for (int k = 0; k < 64; k++)
        w[k] = Wh[(64 * half + k) * HH + j];

    if (t < HH) sh[0][t] = 0.f;
    const float* xip = g_xi + (size_t)b * SS * HH + j;
    float*       hp  = g_h  + (size_t)b * SS * HH + j;
    __syncthreads();

    // 2-deep xi prefetch: value consumed at step s was loaded at step s-2,
    // so DRAM/L2 latency is hidden behind two full steps.
    float xi0 = xip[0];
    float xi1 = xip[HH];
    int cur = 0;
    for (int s = 0; s < SS; s++) {
        float xi2 = (s + 2 < SS) ? xip[(size_t)(s + 2) * HH] : 0.f;

        // 64 FMAs over this thread's K-half, 4 independent chains.
        const float4* sh4 = (const float4*)(sh[cur] + 64 * half);
        float a0 = 0.f, a1 = 0.f, a2 = 0.f, a3 = 0.f;
#pragma unroll
        for (int k4 = 0; k4 < 16; k4++) {
            float4 hv = sh4[k4];
            a0 = fmaf(hv.x, w[4 * k4 + 0], a0);
            a1 = fmaf(hv.y, w[4 * k4 + 1], a1);
            a2 = fmaf(hv.z, w[4 * k4 + 2], a2);
            a3 = fmaf(hv.w, w[4 * k4 + 3], a3);
        }
        float part = (a0 + a1) + (a2 + a3);
        // Combine the two K-halves (adjacent lanes) -> full dot in both lanes.
        part += __shfl_xor_sync(0xffffffffu, part, 1);

        if (half == 0) {
            float v  = xi0 + part;
            // tanh(v) = 1 - 2/(exp(2v)+1) via MUFU.EX2 + MUFU.RCP (~1e-7 rel).
            float vc = fminf(fmaxf(v, -15.f), 15.f);
            float e;
            asm("ex2.approx.f32 %0, %1;" : "=f"(e) : "f"(vc * 2.885390082f));
            float r;
            asm("rcp.approx.f32 %0, %1;" : "=f"(r) : "f"(e + 1.f));
            float hn = fmaxf(fmaf(-2.f, r, 1.f), 0.f);

            sh[cur ^ 1][j] = hn;       // write the OTHER buffer
            hp[(size_t)s * HH] = hn;   // history for the output GEMM
        }
        xi0 = xi1;
        xi1 = xi2;
        __syncthreads();               // single barrier: write -> next read
        cur ^= 1;
    }
}

extern "C" void kernel_launch(void* const* d_in, const int* in_sizes, int n_in,
                              void* d_out, int out_size) {
    const float* x  = (const float*)d_in[0];
    const float* Wi = (const float*)d_in[1];
    const float* Wh = (const float*)d_in[2];
    const float* b  = (const float*)d_in[3];
    const float* Wo = (const float*)d_in[4];
    const float* bo = (const float*)d_in[5];
    float* y = (float*)d_out;

    float* xi_ptr = nullptr;
    float* h_ptr  = nullptr;
    cudaGetSymbolAddress((void**)&xi_ptr, g_xi);
    cudaGetSymbolAddress((void**)&h_ptr,  g_h);

    const size_t smem = (128 * 128 + 64 * 132) * sizeof(float);  // ~97 KB
    cudaFuncSetAttribute(gemm_k128, cudaFuncAttributeMaxDynamicSharedMemorySize,
                         (int)smem);

    // 1) xi = x @ Wi + b
    gemm_k128<<<MM / 64, 256, smem>>>(x, Wi, b, xi_ptr);
    // 2) sequential recurrence (parallel over batch)
    rnn_kernel<<<BB, 256>>>(Wh);
    // 3) y = h @ Wo + bo
    gemm_k128<<<MM / 64, 256, smem>>>(h_ptr, Wo, bo, y);
}